// round 9
// baseline (speedup 1.0000x reference)
#include <cuda_runtime.h>
#include <cuda_bf16.h>
#include <cstdint>

// Problem constants
#define NB 8
#define NL 2048
#define ND 128
#define EPSN 1e-8f
#define MARGIN 0.02f
#define CCAP 64

// ---------------- scratch (no allocation allowed) ----------------
__device__ __align__(128) float g_cn[NB * NL * ND];            // normalized ctx
__device__ __align__(128) float g_en[NB * NL * ND];            // normalized ent
__device__ __align__(128) __nv_bfloat16 g_cnbf[NB * NL * ND];  // bf16(cn)
__device__ __align__(128) __nv_bfloat16 g_enbf[NB * NL * ND];  // bf16(en)
__device__ __align__(128) float g_scn[NB * NL];                // s(cn row)
__device__ __align__(128) float g_sen[NB * NL];                // s(en row)
__device__ __align__(128) float g_pv[NB * NL * 2];             // per-half best sim
__device__ __align__(128) int   g_pi[NB * NL * 2];             // per-half best idx

// ---------------- PTX helpers (compute_103-safe) ----------------
__device__ __forceinline__ uint32_t smem_u32(const void* p) {
    uint32_t a;
    asm("{ .reg .u64 t; cvta.to.shared.u64 t, %1; cvt.u32.u64 %0, t; }"
        : "=r"(a) : "l"(p));
    return a;
}
__device__ __forceinline__ void ldmA(uint32_t* a, uint32_t addr) {
    asm volatile("ldmatrix.sync.aligned.m8n8.x4.shared.b16 {%0,%1,%2,%3}, [%4];"
                 : "=r"(a[0]), "=r"(a[1]), "=r"(a[2]), "=r"(a[3]) : "r"(addr));
}
__device__ __forceinline__ void ldmB(uint32_t* b, uint32_t addr) {
    asm volatile("ldmatrix.sync.aligned.m8n8.x2.shared.b16 {%0,%1}, [%2];"
                 : "=r"(b[0]), "=r"(b[1]) : "r"(addr));
}
__device__ __forceinline__ void mma16816(float* c, const uint32_t* a,
                                         const uint32_t* b) {
    asm volatile(
        "mma.sync.aligned.m16n8k16.row.col.f32.bf16.bf16.f32 "
        "{%0,%1,%2,%3}, {%4,%5,%6,%7}, {%8,%9}, {%0,%1,%2,%3};"
        : "+f"(c[0]), "+f"(c[1]), "+f"(c[2]), "+f"(c[3])
        : "r"(a[0]), "r"(a[1]), "r"(a[2]), "r"(a[3]), "r"(b[0]), "r"(b[1]));
}
#define CP_ASYNC16(dst, src) \
    asm volatile("cp.async.cg.shared.global [%0], [%1], 16;" :: "r"(dst), "l"(src))
#define CP_COMMIT() asm volatile("cp.async.commit_group;")
#define CP_WAIT(n)  asm volatile("cp.async.wait_group %0;" :: "n"(n))

// =================================================================
// Stage 1: L2-normalize; emit fp32 rows + bf16 rows (proven, 9.2us).
// =================================================================
__global__ void norm_kernel(const float* __restrict__ ctx) {
    int gwarp = (blockIdx.x * blockDim.x + threadIdx.x) >> 5;
    int lane  = threadIdx.x & 31;
    if (gwarp >= 2 * NB * NL) return;
    int which = gwarp >> 14;
    int r     = gwarp & (NB * NL - 1);
    int b = r >> 11, l = r & (NL - 1);
    const float4* src =
        (const float4*)(ctx + ((size_t)(b * 2 + which) * NL + l) * ND);
    float4 v = src[lane];
    float s = v.x * v.x + v.y * v.y + v.z * v.z + v.w * v.w;
#pragma unroll
    for (int o = 16; o; o >>= 1) s += __shfl_xor_sync(0xffffffffu, s, o);
    float inv = 1.0f / fmaxf(sqrtf(s), EPSN);
    float4 o4 = make_float4(v.x * inv, v.y * inv, v.z * inv, v.w * inv);
    float* dst = which ? g_en : g_cn;
    ((float4*)(dst + (size_t)r * ND))[lane] = o4;

    __nv_bfloat16* bdst = which ? g_enbf : g_cnbf;
    __nv_bfloat162* hp = (__nv_bfloat162*)(bdst + (size_t)r * ND + lane * 4);
    hp[0] = __halves2bfloat162(__float2bfloat16(o4.x), __float2bfloat16(o4.y));
    hp[1] = __halves2bfloat162(__float2bfloat16(o4.z), __float2bfloat16(o4.w));
}

// =================================================================
// Stage 2: per-row MLP scalar s(row) = relu(row.W1+b1)@W2 for all
// 32768 rows. Same as R8 (passing) except 128 rows/block (grid 256).
// =================================================================
#define W1S 132
#define SMLP_ROWS (128 * W1S)
#define SMLP_PART (SMLP_ROWS + 16 * 128)
#define SMLP_TOTAL ((SMLP_PART + 64) * 4)

__global__ __launch_bounds__(128) void smlp_kernel(
    const float* __restrict__ W1, const float* __restrict__ b1,
    const float* __restrict__ W2) {
    extern __shared__ float sm[];
    float* W1t  = sm;
    float* rows = sm + SMLP_ROWS;
    float* part = sm + SMLP_PART;

    int tid = threadIdx.x, lane = tid & 31, wp = tid >> 5;

#pragma unroll
    for (int i = 0; i < 128; ++i) {
        int flat = i * 128 + tid;
        int j = flat & 127, k = flat >> 7;
        W1t[j * W1S + k] = W1[k * 128 + j];
    }
    float bias = b1[tid];
    float w2   = W2[tid];

    int r0 = blockIdx.x * 128;
    for (int g0 = 0; g0 < 128; g0 += 16) {
        __syncthreads();
#pragma unroll
        for (int i = 0; i < 16; ++i) {
            int flat = i * 128 + tid;
            int r = flat >> 7, k = flat & 127;
            int vr = r0 + g0 + r;
            const float* src = (vr < NB * NL)
                ? g_cn + (size_t)vr * ND
                : g_en + (size_t)(vr - NB * NL) * ND;
            rows[r * 128 + k] = src[k];
        }
        __syncthreads();

        float acc[16];
#pragma unroll
        for (int r = 0; r < 16; ++r) acc[r] = bias;
#pragma unroll 4
        for (int kq = 0; kq < 32; ++kq) {
            float4 w4 = *(const float4*)(W1t + tid * W1S + kq * 4);
#pragma unroll
            for (int r = 0; r < 16; ++r) {
                float4 x = *(const float4*)(rows + r * 128 + kq * 4);
                acc[r] += w4.x * x.x + w4.y * x.y + w4.z * x.z + w4.w * x.w;
            }
        }
#pragma unroll
        for (int r = 0; r < 16; ++r) {
            float c = fmaxf(acc[r], 0.0f) * w2;
#pragma unroll
            for (int o = 16; o; o >>= 1) c += __shfl_xor_sync(0xffffffffu, c, o);
            if (lane == 0) part[r * 4 + wp] = c;
        }
        __syncthreads();
        if (tid < 16) {
            float s = part[tid * 4] + part[tid * 4 + 1] +
                      part[tid * 4 + 2] + part[tid * 4 + 3];
            int vr = r0 + g0 + tid;
            if (vr < NB * NL) g_scn[vr] = s;
            else              g_sen[vr - NB * NL] = s;
        }
    }
}

// =================================================================
// Stage 3: HMMA sim-GEMM + fused argmax, 2 CTAs/SM.
// M=128/CTA; blockIdx.z selects en half [half*1024, half*1024+1024).
// 256 threads: wy=w>>1 (4 m-slots of 32), wx=w&1 (2 n-slots of 32),
// warp tile 32x32, n-tile 64, 16 tiles. No candV filter: all
// appended candidates are rescored exactly in fp32.
// Writes per-half (best sim, idx) to g_pv/g_pi.
// =================================================================
#define LDB 272
#define SM_AT   0                           // 128*272 = 34816
#define SM_BT0  34816                       // 64*272 = 17408
#define SM_BT1  52224                       // 17408
#define SM_CI   69632                       // 128*64*4 = 32768
#define SM_CNT  102400                      // 512
#define SM_RED  102912                      // 256 f + 256 i = 2048
#define SM_SIM_TOTAL 104960

__global__ __launch_bounds__(256, 2) void simarg_kernel() {
    extern __shared__ char smc[];
    int*   candI = (int*)(smc + SM_CI);
    int*   cnt   = (int*)(smc + SM_CNT);
    float* redV  = (float*)(smc + SM_RED);
    int*   redI  = (int*)(smc + SM_RED + 1024);

    int tid = threadIdx.x, w = tid >> 5, lane = tid & 31;
    int wy = w >> 1, wx = w & 1;
    int g = lane >> 2, t = lane & 3;
    int b = blockIdx.y, l0 = blockIdx.x * 128;
    int half = blockIdx.z;
    int n0 = half * 1024;

    if (tid < 128) cnt[tid] = 0;

    // load A tile (128 rows x 256B), proven copy pattern
    const uint4* asrc = (const uint4*)(g_cnbf + ((size_t)b * NL + l0) * ND);
#pragma unroll
    for (int i = tid; i < 2048; i += 256) {
        int row = i >> 4, c = i & 15;
        *(uint4*)(smc + SM_AT + row * LDB + c * 16) = asrc[row * 16 + c];
    }

    const char* esrc = (const char*)(g_enbf + ((size_t)b * NL + n0) * ND);
    uint32_t sb = smem_u32(smc);

    // prefetch B tile 0 (64 rows x 256B)
#pragma unroll
    for (int i = tid; i < 1024; i += 256) {
        int row = i >> 4, c = i & 15;
        CP_ASYNC16(sb + SM_BT0 + row * LDB + c * 16,
                   esrc + (size_t)row * 256 + c * 16);
    }
    CP_COMMIT();

    uint32_t aaddr = sb + SM_AT + (32 * wy + (lane & 15)) * LDB + (lane >> 4) * 16;
    uint32_t boff  = (lane & 7) * LDB + ((lane >> 3) & 1) * 16 + wx * 32 * LDB;

    float rmax[2][2] = {{-2.0f, -2.0f}, {-2.0f, -2.0f}};

    for (int mt = 0; mt < 16; ++mt) {
        int cur = mt & 1;
        if (mt + 1 < 16) {
            int nb_ = SM_BT0 + ((mt + 1) & 1) * 17408;
#pragma unroll
            for (int i = tid; i < 1024; i += 256) {
                int row = i >> 4, c = i & 15;
                CP_ASYNC16(sb + nb_ + row * LDB + c * 16,
                           esrc + ((size_t)(mt + 1) * 64 + row) * 256 + c * 16);
            }
            CP_COMMIT();
            CP_WAIT(1);
        } else {
            CP_WAIT(0);
        }
        __syncthreads();

        uint32_t bbase = sb + SM_BT0 + cur * 17408 + boff;

        float acc[2][4][4];
#pragma unroll
        for (int f = 0; f < 2; ++f)
#pragma unroll
            for (int j = 0; j < 4; ++j)
#pragma unroll
                for (int c = 0; c < 4; ++c) acc[f][j][c] = 0.0f;

#pragma unroll
        for (int kc = 0; kc < 8; ++kc) {
            uint32_t a0[4], a1[4];
            ldmA(a0, aaddr + kc * 32);
            ldmA(a1, aaddr + 16 * LDB + kc * 32);
#pragma unroll
            for (int j = 0; j < 4; ++j) {
                uint32_t bb[2];
                ldmB(bb, bbase + j * 8 * LDB + kc * 32);
                mma16816(acc[0][j], a0, bb);
                mma16816(acc[1][j], a1, bb);
            }
        }

        // epilogue: running max + candidate append (no value storage)
#pragma unroll
        for (int f = 0; f < 2; ++f)
#pragma unroll
            for (int h = 0; h < 2; ++h) {
                float tm = -2.0f;
#pragma unroll
                for (int j = 0; j < 4; ++j)
                    tm = fmaxf(tm, fmaxf(acc[f][j][2 * h], acc[f][j][2 * h + 1]));
                tm = fmaxf(tm, __shfl_xor_sync(0xffffffffu, tm, 1));
                tm = fmaxf(tm, __shfl_xor_sync(0xffffffffu, tm, 2));
                float nm = fmaxf(rmax[f][h], tm);
                rmax[f][h] = nm;
                float thr = nm - MARGIN;
                int r = 32 * wy + 16 * f + 8 * h + g;
#pragma unroll
                for (int j = 0; j < 4; ++j)
#pragma unroll
                    for (int c = 0; c < 2; ++c) {
                        float v = acc[f][j][2 * h + c];
                        if (v >= thr) {
                            int pos = atomicAdd(&cnt[r], 1);
                            if (pos < CCAP) {
                                candI[r * CCAP + pos] =
                                    n0 + mt * 64 + wx * 32 + j * 8 + 2 * t + c;
                            }
                        }
                    }
            }
        __syncthreads();  // buf (cur) fully consumed before refill
    }

    // exact fp32 rescore of ALL appended candidates: 2 threads per row
    {
        int r = tid >> 1;
        int n = min(cnt[r], CCAP);
        float bv = -1e30f;
        int bi = 0x7fffffff;
        const float4* xa = (const float4*)(g_cn + ((size_t)b * NL + l0 + r) * ND);
        for (int e = (tid & 1); e < n; e += 2) {
            int m = candI[r * CCAP + e];
            const float4* xb = (const float4*)(g_en + ((size_t)b * NL + m) * ND);
            float s0 = 0, s1 = 0, s2 = 0, s3 = 0;
#pragma unroll
            for (int q = 0; q < 32; ++q) {
                float4 A = xa[q];
                float4 Bv = xb[q];
                s0 += A.x * Bv.x; s1 += A.y * Bv.y;
                s2 += A.z * Bv.z; s3 += A.w * Bv.w;
            }
            float s = (s0 + s1) + (s2 + s3);
            if (s > bv || (s == bv && m < bi)) { bv = s; bi = m; }
        }
        redV[tid] = bv;
        redI[tid] = bi;
        __syncthreads();
        if (tid < 128) {
            float v0 = redV[tid * 2], v1 = redV[tid * 2 + 1];
            int i0 = redI[tid * 2], i1 = redI[tid * 2 + 1];
            float bvf = (v1 > v0 || (v1 == v0 && i1 < i0)) ? v1 : v0;
            int bif   = (v1 > v0 || (v1 == v0 && i1 < i0)) ? i1 : i0;
            int tok = b * NL + l0 + tid;
            g_pv[tok * 2 + half] = bvf;
            g_pi[tok * 2 + half] = bif;
        }
    }
}

// =================================================================
// Stage 4: merge halves + final output.
// half-0 indices are always lower, so strict > prefers half 0 on
// ties (first-occurrence semantics preserved).
// =================================================================
__global__ void merge_kernel(const float* __restrict__ b2,
                             float* __restrict__ out) {
    int tok = blockIdx.x * 256 + threadIdx.x;
    if (tok >= NB * NL) return;
    float v0 = g_pv[tok * 2], v1 = g_pv[tok * 2 + 1];
    int   i0 = g_pi[tok * 2], i1 = g_pi[tok * 2 + 1];
    int best = (v1 > v0) ? i1 : i0;
    out[tok] = g_scn[tok] + g_sen[(tok & ~(NL - 1)) + best] + 2.0f * b2[0];
}

// =================================================================
// launch
// =================================================================
extern "C" void kernel_launch(void* const* d_in, const int* in_sizes, int n_in,
                              void* d_out, int out_size) {
    const float* context = (const float*)d_in[0];
    const float* W1      = (const float*)d_in[1];
    const float* b1      = (const float*)d_in[2];
    const float* W2      = (const float*)d_in[3];
    const float* b2      = (const float*)d_in[4];
    float* out           = (float*)d_out;

    {
        int warps = 2 * NB * NL;
        int threads = 256;
        int blocks = (warps * 32 + threads - 1) / threads;
        norm_kernel<<<blocks, threads>>>(context);
    }
    {
        cudaFuncSetAttribute(smlp_kernel,
                             cudaFuncAttributeMaxDynamicSharedMemorySize,
                             SMLP_TOTAL);
        smlp_kernel<<<2 * NB * NL / 128, 128, SMLP_TOTAL>>>(W1, b1, W2);
    }
    {
        cudaFuncSetAttribute(simarg_kernel,
                             cudaFuncAttributeMaxDynamicSharedMemorySize,
                             SM_SIM_TOTAL);
        dim3 grid(NL / 128, NB, 2);
        simarg_kernel<<<grid, 256, SM_SIM_TOTAL>>>();
    }
    {
        merge_kernel<<<(NB * NL + 255) / 256, 256>>>(b2, out);
    }
}

// round 10
// speedup vs baseline: 1.0279x; 1.0279x over previous
#include <cuda_runtime.h>
#include <cuda_bf16.h>
#include <cstdint>

// Problem constants
#define NB 8
#define NL 2048
#define ND 128
#define EPSN 1e-8f
#define MARGIN 0.02f
#define CCAP 48

// ---------------- scratch (no allocation allowed) ----------------
__device__ __align__(128) float g_cn[NB * NL * ND];            // normalized ctx
__device__ __align__(128) float g_en[NB * NL * ND];            // normalized ent
__device__ __align__(128) __nv_bfloat16 g_cnbf[NB * NL * ND];  // bf16(cn)
__device__ __align__(128) __nv_bfloat16 g_enbf[NB * NL * ND];  // bf16(en)
__device__ __align__(128) float g_scn[NB * NL];                // s(cn row)
__device__ __align__(128) float g_sen[NB * NL];                // s(en row)

// ---------------- PTX helpers (compute_103-safe) ----------------
__device__ __forceinline__ uint32_t smem_u32(const void* p) {
    uint32_t a;
    asm("{ .reg .u64 t; cvta.to.shared.u64 t, %1; cvt.u32.u64 %0, t; }"
        : "=r"(a) : "l"(p));
    return a;
}
__device__ __forceinline__ void ldmA(uint32_t* a, uint32_t addr) {
    asm volatile("ldmatrix.sync.aligned.m8n8.x4.shared.b16 {%0,%1,%2,%3}, [%4];"
                 : "=r"(a[0]), "=r"(a[1]), "=r"(a[2]), "=r"(a[3]) : "r"(addr));
}
__device__ __forceinline__ void ldmB(uint32_t* b, uint32_t addr) {
    asm volatile("ldmatrix.sync.aligned.m8n8.x2.shared.b16 {%0,%1}, [%2];"
                 : "=r"(b[0]), "=r"(b[1]) : "r"(addr));
}
__device__ __forceinline__ void mma16816(float* c, const uint32_t* a,
                                         const uint32_t* b) {
    asm volatile(
        "mma.sync.aligned.m16n8k16.row.col.f32.bf16.bf16.f32 "
        "{%0,%1,%2,%3}, {%4,%5,%6,%7}, {%8,%9}, {%0,%1,%2,%3};"
        : "+f"(c[0]), "+f"(c[1]), "+f"(c[2]), "+f"(c[3])
        : "r"(a[0]), "r"(a[1]), "r"(a[2]), "r"(a[3]), "r"(b[0]), "r"(b[1]));
}
#define CP_ASYNC16(dst, src) \
    asm volatile("cp.async.cg.shared.global [%0], [%1], 16;" :: "r"(dst), "l"(src))
#define CP_COMMIT() asm volatile("cp.async.commit_group;")
#define CP_WAIT(n)  asm volatile("cp.async.wait_group %0;" :: "n"(n))

// =================================================================
// Stage 1: L2-normalize; emit fp32 rows + bf16 rows (proven, 9.2us).
// =================================================================
__global__ void norm_kernel(const float* __restrict__ ctx) {
    int gwarp = (blockIdx.x * blockDim.x + threadIdx.x) >> 5;
    int lane  = threadIdx.x & 31;
    if (gwarp >= 2 * NB * NL) return;
    int which = gwarp >> 14;
    int r     = gwarp & (NB * NL - 1);
    int b = r >> 11, l = r & (NL - 1);
    const float4* src =
        (const float4*)(ctx + ((size_t)(b * 2 + which) * NL + l) * ND);
    float4 v = src[lane];
    float s = v.x * v.x + v.y * v.y + v.z * v.z + v.w * v.w;
#pragma unroll
    for (int o = 16; o; o >>= 1) s += __shfl_xor_sync(0xffffffffu, s, o);
    float inv = 1.0f / fmaxf(sqrtf(s), EPSN);
    float4 o4 = make_float4(v.x * inv, v.y * inv, v.z * inv, v.w * inv);
    float* dst = which ? g_en : g_cn;
    ((float4*)(dst + (size_t)r * ND))[lane] = o4;

    __nv_bfloat16* bdst = which ? g_enbf : g_cnbf;
    __nv_bfloat162* hp = (__nv_bfloat162*)(bdst + (size_t)r * ND + lane * 4);
    hp[0] = __halves2bfloat162(__float2bfloat16(o4.x), __float2bfloat16(o4.y));
    hp[1] = __halves2bfloat162(__float2bfloat16(o4.z), __float2bfloat16(o4.w));
}

// =================================================================
// Stage 2: per-row MLP scalar s(row) = relu(row.W1+b1)@W2 for all
// 32768 rows. 256 threads (2 warps/SMSP), grid 128 = one wave,
// 256 rows/block in chunks of 32. Thread-half hg owns 16 rows;
// neuron j = tid & 127. Inner math identical to the R8 pass.
// =================================================================
#define W1S 132
#define SMLP_ROWS (128 * W1S)               // float offset of rows[]
#define SMLP_PART (SMLP_ROWS + 32 * 128)    // float offset of part[]
#define SMLP_TOTAL ((SMLP_PART + 128 + 32) * 4)

__global__ __launch_bounds__(256) void smlp_kernel(
    const float* __restrict__ W1, const float* __restrict__ b1,
    const float* __restrict__ W2) {
    extern __shared__ float sm[];
    float* W1t  = sm;
    float* rows = sm + SMLP_ROWS;
    float* part = sm + SMLP_PART;

    int tid = threadIdx.x, lane = tid & 31, wp = tid >> 5;
    int hg = tid >> 7;          // row-half (0/1)
    int j  = tid & 127;         // neuron
    int wq = wp & 3;            // warp within half-group

    // load W1 transposed: W1t[j][k] = W1[k][j]
#pragma unroll
    for (int i = 0; i < 64; ++i) {
        int flat = i * 256 + tid;
        int jj = flat & 127, k = flat >> 7;
        W1t[jj * W1S + k] = W1[k * 128 + jj];
    }
    float bias = b1[j];
    float w2   = W2[j];

    int r0 = blockIdx.x * 256;
    for (int g0 = 0; g0 < 256; g0 += 32) {
        __syncthreads();
        // load 32 rows (coalesced, 16 iters x 256 threads)
#pragma unroll
        for (int i = 0; i < 16; ++i) {
            int flat = i * 256 + tid;
            int r = flat >> 7, k = flat & 127;
            int vr = r0 + g0 + r;
            const float* src = (vr < NB * NL)
                ? g_cn + (size_t)vr * ND
                : g_en + (size_t)(vr - NB * NL) * ND;
            rows[r * 128 + k] = src[k];
        }
        __syncthreads();

        float acc[16];
#pragma unroll
        for (int r = 0; r < 16; ++r) acc[r] = bias;
#pragma unroll 4
        for (int kq = 0; kq < 32; ++kq) {
            float4 w4 = *(const float4*)(W1t + j * W1S + kq * 4);
#pragma unroll
            for (int r = 0; r < 16; ++r) {
                float4 x = *(const float4*)(rows + (hg * 16 + r) * 128 + kq * 4);
                acc[r] += w4.x * x.x + w4.y * x.y + w4.z * x.z + w4.w * x.w;
            }
        }
#pragma unroll
        for (int r = 0; r < 16; ++r) {
            float c = fmaxf(acc[r], 0.0f) * w2;
#pragma unroll
            for (int o = 16; o; o >>= 1) c += __shfl_xor_sync(0xffffffffu, c, o);
            if (lane == 0) part[(hg * 16 + r) * 4 + wq] = c;
        }
        __syncthreads();
        if (tid < 32) {
            float s = part[tid * 4] + part[tid * 4 + 1] +
                      part[tid * 4 + 2] + part[tid * 4 + 3];
            int vr = r0 + g0 + tid;
            if (vr < NB * NL) g_scn[vr] = s;
            else              g_sen[vr - NB * NL] = s;
        }
    }
}

// =================================================================
// Stage 3: HMMA sim-GEMM + fused argmax — BYTE-IDENTICAL to the R6/R8
// pass (76.7us measured): M=128, 3-stage cp.async pipeline, direct
// output via g_scn/g_sen.
// =================================================================
#define LDB 272
#define SM_AT   0                           // 34816
#define SM_BT0  34816                       // 3 buffers x 34816
#define SM_CS   139264                      // 128*48*4 = 24576
#define SM_CI   163840                      // 24576
#define SM_CNT  188416                      // 512
#define SM_HM   188928                      // 1024
#define SM_SIM_TOTAL 189952

__global__ __launch_bounds__(256, 1) void simarg_kernel(
    const float* __restrict__ b2, float* __restrict__ out) {
    extern __shared__ char smc[];
    float* candV = (float*)(smc + SM_CS);
    int*   candI = (int*)(smc + SM_CI);
    int*   cnt   = (int*)(smc + SM_CNT);
    float* hmax  = (float*)(smc + SM_HM);

    int tid = threadIdx.x, w = tid >> 5, lane = tid & 31;
    int wy = w >> 1, wx = w & 1;
    int g = lane >> 2, t = lane & 3;
    int b = blockIdx.y, l0 = blockIdx.x * 128;

    if (tid < 128) cnt[tid] = 0;

    // load A tile (plain vectorized copy)
    const uint4* asrc = (const uint4*)(g_cnbf + ((size_t)b * NL + l0) * ND);
#pragma unroll
    for (int i = tid; i < 2048; i += 256) {
        int row = i >> 4, c = i & 15;
        *(uint4*)(smc + SM_AT + row * LDB + c * 16) = asrc[row * 16 + c];
    }

    const char* esrc = (const char*)(g_enbf + (size_t)b * NL * ND);
    uint32_t sb = smem_u32(smc);

    // prefetch B tiles 0 and 1
#pragma unroll
    for (int q = 0; q < 2; ++q) {
#pragma unroll
        for (int i = tid; i < 2048; i += 256) {
            int row = i >> 4, c = i & 15;
            CP_ASYNC16(sb + SM_BT0 + q * 34816 + row * LDB + c * 16,
                       esrc + ((size_t)q * 128 + row) * 256 + c * 16);
        }
        CP_COMMIT();
    }

    uint32_t aaddr = sb + SM_AT + ((32 * wy + (lane & 15)) * LDB + (lane >> 4) * 16);
    uint32_t baddr0 = ((lane & 7)) * LDB + ((lane >> 3) & 1) * 16;

    float rmax[2][2] = {{-2.0f, -2.0f}, {-2.0f, -2.0f}};

    for (int mt = 0; mt < 16; ++mt) {
        if (mt < 15) { CP_WAIT(1); } else { CP_WAIT(0); }
        __syncthreads();

        uint32_t bbase = sb + SM_BT0 + (mt % 3) * 34816 + baddr0 + wx * 64 * LDB;

        float acc[2][8][4];
#pragma unroll
        for (int f = 0; f < 2; ++f)
#pragma unroll
            for (int j = 0; j < 8; ++j)
#pragma unroll
                for (int c = 0; c < 4; ++c) acc[f][j][c] = 0.0f;

#pragma unroll
        for (int kc = 0; kc < 8; ++kc) {
            uint32_t a0[4], a1[4];
            ldmA(a0, aaddr + kc * 32);
            ldmA(a1, aaddr + 16 * LDB + kc * 32);
#pragma unroll
            for (int j = 0; j < 8; ++j) {
                uint32_t bb[2];
                ldmB(bb, bbase + j * 8 * LDB + kc * 32);
                mma16816(acc[0][j], a0, bb);
                mma16816(acc[1][j], a1, bb);
            }
        }

        // epilogue: running max + candidate append (R3-proven)
#pragma unroll
        for (int f = 0; f < 2; ++f)
#pragma unroll
            for (int h = 0; h < 2; ++h) {
                float tm = -2.0f;
#pragma unroll
                for (int j = 0; j < 8; ++j)
                    tm = fmaxf(tm, fmaxf(acc[f][j][2 * h], acc[f][j][2 * h + 1]));
                tm = fmaxf(tm, __shfl_xor_sync(0xffffffffu, tm, 1));
                tm = fmaxf(tm, __shfl_xor_sync(0xffffffffu, tm, 2));
                float nm = fmaxf(rmax[f][h], tm);
                rmax[f][h] = nm;
                float thr = nm - MARGIN;
                int r = 32 * wy + 16 * f + 8 * h + g;
#pragma unroll
                for (int j = 0; j < 8; ++j)
#pragma unroll
                    for (int c = 0; c < 2; ++c) {
                        float v = acc[f][j][2 * h + c];
                        if (v >= thr) {
                            int pos = atomicAdd(&cnt[r], 1);
                            if (pos < CCAP) {
                                candV[r * CCAP + pos] = v;
                                candI[r * CCAP + pos] =
                                    mt * 128 + wx * 64 + j * 8 + 2 * t + c;
                            }
                        }
                    }
            }
        __syncthreads();  // all reads of buf (mt%3) done

        if (mt + 2 < 16) {  // prefetch tile mt+2 into buf (mt+2)%3
            int nb_ = SM_BT0 + ((mt + 2) % 3) * 34816;
#pragma unroll
            for (int i = tid; i < 2048; i += 256) {
                int row = i >> 4, c = i & 15;
                CP_ASYNC16(sb + nb_ + row * LDB + c * 16,
                           esrc + ((size_t)(mt + 2) * 128 + row) * 256 + c * 16);
            }
            CP_COMMIT();
        }
    }

    // publish per-warp-half row maxima
    if (t == 0) {
#pragma unroll
        for (int f = 0; f < 2; ++f)
#pragma unroll
            for (int h = 0; h < 2; ++h)
                hmax[(32 * wy + 16 * f + 8 * h + g) * 2 + wx] = rmax[f][h];
    }
    __syncthreads();

    // filter + exact fp32 rescore: 2 threads per row; then write output
    {
        int r = tid >> 1;
        float Mb = fmaxf(hmax[r * 2], hmax[r * 2 + 1]);
        float thr = Mb - MARGIN;
        int n = min(cnt[r], CCAP);
        float bv = -1e30f;
        int bi = 0x7fffffff;
        const float4* xa = (const float4*)(g_cn + ((size_t)b * NL + l0 + r) * ND);
        for (int e = (tid & 1); e < n; e += 2) {
            if (candV[r * CCAP + e] < thr) continue;
            int m = candI[r * CCAP + e];
            const float4* xb = (const float4*)(g_en + ((size_t)b * NL + m) * ND);
            float s0 = 0, s1 = 0, s2 = 0, s3 = 0;
#pragma unroll
            for (int q = 0; q < 32; ++q) {
                float4 A = xa[q];
                float4 Bv = xb[q];
                s0 += A.x * Bv.x; s1 += A.y * Bv.y;
                s2 += A.z * Bv.z; s3 += A.w * Bv.w;
            }
            float s = (s0 + s1) + (s2 + s3);
            if (s > bv || (s == bv && m < bi)) { bv = s; bi = m; }
        }
        __syncthreads();
        candV[tid] = bv;
        candI[tid] = bi;
        __syncthreads();
        if (tid < 128) {
            float v0 = candV[tid * 2], v1 = candV[tid * 2 + 1];
            int i0 = candI[tid * 2], i1 = candI[tid * 2 + 1];
            int best = (v1 > v0 || (v1 == v0 && i1 < i0)) ? i1 : i0;
            float bb2 = b2[0];
            out[b * NL + l0 + tid] = g_scn[b * NL + l0 + tid] +
                                     g_sen[b * NL + best] + 2.0f * bb2;
        }
    }
}

// =================================================================
// launch
// =================================================================
extern "C" void kernel_launch(void* const* d_in, const int* in_sizes, int n_in,
                              void* d_out, int out_size) {
    const float* context = (const float*)d_in[0];
    const float* W1      = (const float*)d_in[1];
    const float* b1      = (const float*)d_in[2];
    const float* W2      = (const float*)d_in[3];
    const float* b2      = (const float*)d_in[4];
    float* out           = (float*)d_out;

    {
        int warps = 2 * NB * NL;
        int threads = 256;
        int blocks = (warps * 32 + threads - 1) / threads;
        norm_kernel<<<blocks, threads>>>(context);
    }
    {
        cudaFuncSetAttribute(smlp_kernel,
                             cudaFuncAttributeMaxDynamicSharedMemorySize,
                             SMLP_TOTAL);
        smlp_kernel<<<2 * NB * NL / 256, 256, SMLP_TOTAL>>>(W1, b1, W2);
    }
    {
        cudaFuncSetAttribute(simarg_kernel,
                             cudaFuncAttributeMaxDynamicSharedMemorySize,
                             SM_SIM_TOTAL);
        dim3 grid(NL / 128, NB);
        simarg_kernel<<<grid, 256, SM_SIM_TOTAL>>>(b2, out);
    }
}

// round 11
// speedup vs baseline: 1.2743x; 1.2397x over previous
#include <cuda_runtime.h>
#include <cuda_bf16.h>
#include <cstdint>

// Problem constants
#define NB 8
#define NL 2048
#define ND 128
#define EPSN 1e-8f
#define MARGIN 0.02f
#define CCAP 48

// ---------------- scratch (no allocation allowed) ----------------
__device__ __align__(128) float g_cn[NB * NL * ND];            // normalized ctx
__device__ __align__(128) float g_en[NB * NL * ND];            // normalized ent
__device__ __align__(128) __nv_bfloat16 g_cnbf[NB * NL * ND];  // bf16(cn)
__device__ __align__(128) __nv_bfloat16 g_enbf[NB * NL * ND];  // bf16(en)
__device__ __align__(128) int g_idx[NB * NL];

// ---------------- PTX helpers (compute_103-safe) ----------------
__device__ __forceinline__ uint32_t smem_u32(const void* p) {
    uint32_t a;
    asm("{ .reg .u64 t; cvta.to.shared.u64 t, %1; cvt.u32.u64 %0, t; }"
        : "=r"(a) : "l"(p));
    return a;
}
__device__ __forceinline__ void ldm4(uint32_t* a, uint32_t addr) {
    asm volatile("ldmatrix.sync.aligned.m8n8.x4.shared.b16 {%0,%1,%2,%3}, [%4];"
                 : "=r"(a[0]), "=r"(a[1]), "=r"(a[2]), "=r"(a[3]) : "r"(addr));
}
__device__ __forceinline__ void mma16816s(float* c, const uint32_t* a,
                                          uint32_t b0, uint32_t b1) {
    asm volatile(
        "mma.sync.aligned.m16n8k16.row.col.f32.bf16.bf16.f32 "
        "{%0,%1,%2,%3}, {%4,%5,%6,%7}, {%8,%9}, {%0,%1,%2,%3};"
        : "+f"(c[0]), "+f"(c[1]), "+f"(c[2]), "+f"(c[3])
        : "r"(a[0]), "r"(a[1]), "r"(a[2]), "r"(a[3]), "r"(b0), "r"(b1));
}
#define CP_ASYNC16(dst, src) \
    asm volatile("cp.async.cg.shared.global [%0], [%1], 16;" :: "r"(dst), "l"(src))
#define CP_COMMIT() asm volatile("cp.async.commit_group;")
#define CP_WAIT(n)  asm volatile("cp.async.wait_group %0;" :: "n"(n))

// =================================================================
// Stage 1: L2-normalize; emit fp32 rows + bf16 rows (proven, 9.5us).
// =================================================================
__global__ void norm_kernel(const float* __restrict__ ctx) {
    int gwarp = (blockIdx.x * blockDim.x + threadIdx.x) >> 5;
    int lane  = threadIdx.x & 31;
    if (gwarp >= 2 * NB * NL) return;
    int which = gwarp >> 14;
    int r     = gwarp & (NB * NL - 1);
    int b = r >> 11, l = r & (NL - 1);
    const float4* src =
        (const float4*)(ctx + ((size_t)(b * 2 + which) * NL + l) * ND);
    float4 v = src[lane];
    float s = v.x * v.x + v.y * v.y + v.z * v.z + v.w * v.w;
#pragma unroll
    for (int o = 16; o; o >>= 1) s += __shfl_xor_sync(0xffffffffu, s, o);
    float inv = 1.0f / fmaxf(sqrtf(s), EPSN);
    float4 o4 = make_float4(v.x * inv, v.y * inv, v.z * inv, v.w * inv);
    float* dst = which ? g_en : g_cn;
    ((float4*)(dst + (size_t)r * ND))[lane] = o4;

    __nv_bfloat16* bdst = which ? g_enbf : g_cnbf;
    __nv_bfloat162* hp = (__nv_bfloat162*)(bdst + (size_t)r * ND + lane * 4);
    hp[0] = __halves2bfloat162(__float2bfloat16(o4.x), __float2bfloat16(o4.y));
    hp[1] = __halves2bfloat162(__float2bfloat16(o4.z), __float2bfloat16(o4.w));
}

// =================================================================
// Stage 2: HMMA sim-GEMM + fused argmax -> g_idx.
// R8-proven shell (M=128, 3-stage cp.async). Deltas vs R8 (isolated
// experiment): (a) B loads via ldmatrix.x4 (2 n-blocks per LDSM),
// (b) explicit next-kc fragment prefetch before current MMAs,
// (c) final write -> g_idx (R3 output path).
// =================================================================
#define LDB 272
#define SM_AT   0                           // 34816
#define SM_BT0  34816                       // 3 buffers x 34816
#define SM_CS   139264                      // 128*48*4 = 24576
#define SM_CI   163840                      // 24576
#define SM_CNT  188416                      // 512
#define SM_HM   188928                      // 1024
#define SM_SIM_TOTAL 189952

__global__ __launch_bounds__(256, 1) void simarg_kernel() {
    extern __shared__ char smc[];
    float* candV = (float*)(smc + SM_CS);
    int*   candI = (int*)(smc + SM_CI);
    int*   cnt   = (int*)(smc + SM_CNT);
    float* hmax  = (float*)(smc + SM_HM);

    int tid = threadIdx.x, w = tid >> 5, lane = tid & 31;
    int wy = w >> 1, wx = w & 1;
    int g = lane >> 2, t = lane & 3;
    int b = blockIdx.y, l0 = blockIdx.x * 128;

    if (tid < 128) cnt[tid] = 0;

    // load A tile (plain vectorized copy)
    const uint4* asrc = (const uint4*)(g_cnbf + ((size_t)b * NL + l0) * ND);
#pragma unroll
    for (int i = tid; i < 2048; i += 256) {
        int row = i >> 4, c = i & 15;
        *(uint4*)(smc + SM_AT + row * LDB + c * 16) = asrc[row * 16 + c];
    }

    const char* esrc = (const char*)(g_enbf + (size_t)b * NL * ND);
    uint32_t sb = smem_u32(smc);

    // prefetch B tiles 0 and 1
#pragma unroll
    for (int q = 0; q < 2; ++q) {
#pragma unroll
        for (int i = tid; i < 2048; i += 256) {
            int row = i >> 4, c = i & 15;
            CP_ASYNC16(sb + SM_BT0 + q * 34816 + row * LDB + c * 16,
                       esrc + ((size_t)q * 128 + row) * 256 + c * 16);
        }
        CP_COMMIT();
    }

    // A fragment address (x4 ldmatrix, 16 rows x k16)
    uint32_t aaddr = sb + SM_AT + ((32 * wy + (lane & 15)) * LDB + (lane >> 4) * 16);
    // B x4 address: lane groups 0-7/8-15 -> n-block j2*2 (k0-7 / k8-15),
    // groups 16-23/24-31 -> n-block j2*2+1.
    uint32_t boff = (lane & 7) * LDB + ((lane >> 3) & 1) * 16 + (lane >> 4) * 8 * LDB;

    float rmax[2][2] = {{-2.0f, -2.0f}, {-2.0f, -2.0f}};

    for (int mt = 0; mt < 16; ++mt) {
        if (mt < 15) { CP_WAIT(1); } else { CP_WAIT(0); }
        __syncthreads();

        uint32_t bbase = sb + SM_BT0 + (mt % 3) * 34816 + boff + wx * 64 * LDB;

        float acc[2][8][4];
#pragma unroll
        for (int f = 0; f < 2; ++f)
#pragma unroll
            for (int j = 0; j < 8; ++j)
#pragma unroll
                for (int c = 0; c < 4; ++c) acc[f][j][c] = 0.0f;

        // fragment-pipelined k-loop
        uint32_t af[2][2][4];
        uint32_t bf[2][4][4];
        ldm4(af[0][0], aaddr);
        ldm4(af[0][1], aaddr + 16 * LDB);
#pragma unroll
        for (int j2 = 0; j2 < 4; ++j2) ldm4(bf[0][j2], bbase + j2 * 16 * LDB);

#pragma unroll
        for (int kc = 0; kc < 8; ++kc) {
            int cb = kc & 1, nx = cb ^ 1;
            if (kc < 7) {
                ldm4(af[nx][0], aaddr + (kc + 1) * 32);
                ldm4(af[nx][1], aaddr + 16 * LDB + (kc + 1) * 32);
#pragma unroll
                for (int j2 = 0; j2 < 4; ++j2)
                    ldm4(bf[nx][j2], bbase + j2 * 16 * LDB + (kc + 1) * 32);
            }
#pragma unroll
            for (int j2 = 0; j2 < 4; ++j2) {
                mma16816s(acc[0][2 * j2],     af[cb][0], bf[cb][j2][0], bf[cb][j2][1]);
                mma16816s(acc[0][2 * j2 + 1], af[cb][0], bf[cb][j2][2], bf[cb][j2][3]);
                mma16816s(acc[1][2 * j2],     af[cb][1], bf[cb][j2][0], bf[cb][j2][1]);
                mma16816s(acc[1][2 * j2 + 1], af[cb][1], bf[cb][j2][2], bf[cb][j2][3]);
            }
        }

        // epilogue: running max + candidate append (R3-proven)
#pragma unroll
        for (int f = 0; f < 2; ++f)
#pragma unroll
            for (int h = 0; h < 2; ++h) {
                float tm = -2.0f;
#pragma unroll
                for (int j = 0; j < 8; ++j)
                    tm = fmaxf(tm, fmaxf(acc[f][j][2 * h], acc[f][j][2 * h + 1]));
                tm = fmaxf(tm, __shfl_xor_sync(0xffffffffu, tm, 1));
                tm = fmaxf(tm, __shfl_xor_sync(0xffffffffu, tm, 2));
                float nm = fmaxf(rmax[f][h], tm);
                rmax[f][h] = nm;
                float thr = nm - MARGIN;
                int r = 32 * wy + 16 * f + 8 * h + g;
#pragma unroll
                for (int j = 0; j < 8; ++j)
#pragma unroll
                    for (int c = 0; c < 2; ++c) {
                        float v = acc[f][j][2 * h + c];
                        if (v >= thr) {
                            int pos = atomicAdd(&cnt[r], 1);
                            if (pos < CCAP) {
                                candV[r * CCAP + pos] = v;
                                candI[r * CCAP + pos] =
                                    mt * 128 + wx * 64 + j * 8 + 2 * t + c;
                            }
                        }
                    }
            }
        __syncthreads();  // all reads of buf (mt%3) done

        if (mt + 2 < 16) {  // prefetch tile mt+2 into buf (mt+2)%3
            int nb_ = SM_BT0 + ((mt + 2) % 3) * 34816;
#pragma unroll
            for (int i = tid; i < 2048; i += 256) {
                int row = i >> 4, c = i & 15;
                CP_ASYNC16(sb + nb_ + row * LDB + c * 16,
                           esrc + ((size_t)(mt + 2) * 128 + row) * 256 + c * 16);
            }
            CP_COMMIT();
        }
    }

    // publish per-warp-half row maxima
    if (t == 0) {
#pragma unroll
        for (int f = 0; f < 2; ++f)
#pragma unroll
            for (int h = 0; h < 2; ++h)
                hmax[(32 * wy + 16 * f + 8 * h + g) * 2 + wx] = rmax[f][h];
    }
    __syncthreads();

    // filter + exact fp32 rescore: 2 threads per row; write g_idx
    {
        int r = tid >> 1;
        float Mb = fmaxf(hmax[r * 2], hmax[r * 2 + 1]);
        float thr = Mb - MARGIN;
        int n = min(cnt[r], CCAP);
        float bv = -1e30f;
        int bi = 0x7fffffff;
        const float4* xa = (const float4*)(g_cn + ((size_t)b * NL + l0 + r) * ND);
        for (int e = (tid & 1); e < n; e += 2) {
            if (candV[r * CCAP + e] < thr) continue;
            int m = candI[r * CCAP + e];
            const float4* xb = (const float4*)(g_en + ((size_t)b * NL + m) * ND);
            float s0 = 0, s1 = 0, s2 = 0, s3 = 0;
#pragma unroll
            for (int q = 0; q < 32; ++q) {
                float4 A = xa[q];
                float4 Bv = xb[q];
                s0 += A.x * Bv.x; s1 += A.y * Bv.y;
                s2 += A.z * Bv.z; s3 += A.w * Bv.w;
            }
            float s = (s0 + s1) + (s2 + s3);
            if (s > bv || (s == bv && m < bi)) { bv = s; bi = m; }
        }
        __syncthreads();
        candV[tid] = bv;
        candI[tid] = bi;
        __syncthreads();
        if (tid < 128) {
            float v0 = candV[tid * 2], v1 = candV[tid * 2 + 1];
            int i0 = candI[tid * 2], i1 = candI[tid * 2 + 1];
            int best = (v1 > v0 || (v1 == v0 && i1 < i0)) ? i1 : i0;
            g_idx[b * NL + l0 + tid] = best;
        }
    }
}

// =================================================================
// Stage 3: per-token 2-row MLP + reduction (R3 verbatim, ~37us).
// =================================================================
#define W1S 132

__global__ __launch_bounds__(128) void mlp_kernel(
    const float* __restrict__ W1, const float* __restrict__ b1,
    const float* __restrict__ W2, const float* __restrict__ b2,
    float* __restrict__ out) {
    extern __shared__ float sm[];
    float* W1t  = sm;
    float* rows = sm + 128 * W1S;
    float* part = sm + 128 * W1S + 16 * 128;

    int tid  = threadIdx.x;
    int lane = tid & 31;
    int wp   = tid >> 5;

#pragma unroll
    for (int i = 0; i < 128; ++i) {
        int flat = i * 128 + tid;
        int j = flat & 127, k = flat >> 7;
        W1t[j * W1S + k] = W1[k * 128 + j];
    }
    float bias = b1[tid];
    float w2   = W2[tid];
    float bb2  = b2[0];

    int tok0 = blockIdx.x * 64;
    for (int g0 = 0; g0 < 64; g0 += 8) {
        __syncthreads();
#pragma unroll
        for (int i = 0; i < 16; ++i) {
            int flat = i * 128 + tid;
            int r = flat >> 7, k = flat & 127;
            int tok = tok0 + g0 + (r >> 1);
            const float* src;
            if (r & 1) {
                int bb = tok >> 11;
                int mi = g_idx[tok];
                src = g_en + ((size_t)(bb << 11) + mi) * ND;
            } else {
                src = g_cn + (size_t)tok * ND;
            }
            rows[r * 128 + k] = src[k];
        }
        __syncthreads();

        float acc[16];
#pragma unroll
        for (int r = 0; r < 16; ++r) acc[r] = bias;

#pragma unroll 4
        for (int kq = 0; kq < 32; ++kq) {
            float4 w4 = *(const float4*)(W1t + tid * W1S + kq * 4);
#pragma unroll
            for (int r = 0; r < 16; ++r) {
                float4 x = *(const float4*)(rows + r * 128 + kq * 4);
                acc[r] += w4.x * x.x + w4.y * x.y + w4.z * x.z + w4.w * x.w;
            }
        }

        float c[8];
#pragma unroll
        for (int g = 0; g < 8; ++g) {
            float h0 = fmaxf(acc[2 * g], 0.0f);
            float h1 = fmaxf(acc[2 * g + 1], 0.0f);
            c[g] = (h0 + h1) * w2;
        }
#pragma unroll
        for (int g = 0; g < 8; ++g) {
            float v = c[g];
#pragma unroll
            for (int o = 16; o; o >>= 1) v += __shfl_xor_sync(0xffffffffu, v, o);
            c[g] = v;
        }
        if (lane == 0) {
#pragma unroll
            for (int g = 0; g < 8; ++g) part[g * 4 + wp] = c[g];
        }
        __syncthreads();
        if (tid < 8) {
            float s = part[tid * 4] + part[tid * 4 + 1] +
                      part[tid * 4 + 2] + part[tid * 4 + 3];
            out[tok0 + g0 + tid] = s + 2.0f * bb2;
        }
    }
}

// =================================================================
// launch
// =================================================================
extern "C" void kernel_launch(void* const* d_in, const int* in_sizes, int n_in,
                              void* d_out, int out_size) {
    const float* context = (const float*)d_in[0];
    const float* W1      = (const float*)d_in[1];
    const float* b1      = (const float*)d_in[2];
    const float* W2      = (const float*)d_in[3];
    const float* b2      = (const float*)d_in[4];
    float* out           = (float*)d_out;

    {
        int warps = 2 * NB * NL;
        int threads = 256;
        int blocks = (warps * 32 + threads - 1) / threads;
        norm_kernel<<<blocks, threads>>>(context);
    }
    {
        cudaFuncSetAttribute(simarg_kernel,
                             cudaFuncAttributeMaxDynamicSharedMemorySize,
                             SM_SIM_TOTAL);
        dim3 grid(NL / 128, NB);
        simarg_kernel<<<grid, 256, SM_SIM_TOTAL>>>();
    }
    {
        size_t smem = (size_t)(128 * W1S + 16 * 128 + 64) * sizeof(float);
        cudaFuncSetAttribute(mlp_kernel,
                             cudaFuncAttributeMaxDynamicSharedMemorySize,
                             (int)smem);
        mlp_kernel<<<NB * NL / 64, 128, smem>>>(W1, b1, W2, b2, out);
    }
}